// round 12
// baseline (speedup 1.0000x reference)
#include <cuda_runtime.h>

#define IN_DIM   8192
#define OUT_DIM  16384
#define TOPK     327
#define ROW_SPLITS 37                 // 16 * 37 = 592 = 4 * 148 SMs → one co-resident wave
#define COL_BLOCKS 16
#define CNT_ONE  (1u << 20)
#define VAL_MASK 0xFFFFFu
#define BBLK     256                  // finalize blocks
#define BCOLS    (OUT_DIM / BBLK)     // 64 columns per finalize block

__device__ __align__(16) unsigned g_overlap[OUT_DIM];  // packed [cnt|val]; self-resets
__device__ __align__(16) int      g_hist[IN_DIM + 4];  // zeroed at start of gemv
__device__ __align__(16) int      g_final[OUT_DIM];    // fully rewritten every launch

__device__ __forceinline__ int warp_incl_scan(int v) {
    int lane = threadIdx.x & 31;
#pragma unroll
    for (int o = 1; o < 32; o <<= 1) {
        int n = __shfl_up_sync(0xffffffffu, v, o);
        if (lane >= o) v += n;
    }
    return v;
}

// ---------------------------------------------------------------------------
// Kernel A: balanced binarized GEMV with fused histogram.
// - zeroes g_hist (blocks 0..32) — safe: first publish is >>30us later
// - each block compacts the FULL x via bitmask + block scan (ordered),
//   takes the even slice [y*na/37, (y+1)*na/37)
// - packed atomic accumulate; 37th arrival publishes g_final + g_hist and
//   self-resets g_overlap[col]
// round(p) for p ~ U[0,1) under round-half-even == (p > 0.5f).
// ---------------------------------------------------------------------------
__global__ void __launch_bounds__(256, 4)
gemv_kernel(const float* __restrict__ p, const int* __restrict__ x) {
    __shared__ int s_act[IN_DIM];      // 32KB: full ordered active list
    __shared__ int s_w[8];
    __shared__ int s_na;

    int t    = threadIdx.x;
    int lane = t & 31;
    int w    = t >> 5;
    int bid  = blockIdx.y * COL_BLOCKS + blockIdx.x;

    // --- zero g_hist for this launch's publishes ---
    if (bid < 32)      g_hist[bid * 256 + t] = 0;
    else if (bid == 32 && t == 0) g_hist[IN_DIM] = 0;

    // --- full-x ordered compaction: thread t owns indices [32t, 32t+32) ---
    unsigned mask = 0;
    {
        const int4* x4 = reinterpret_cast<const int4*>(x);
#pragma unroll
        for (int j = 0; j < 8; j++) {
            int4 v = x4[t * 8 + j];
            mask |= (v.x != 0 ? 1u : 0u) << (j * 4 + 0);
            mask |= (v.y != 0 ? 1u : 0u) << (j * 4 + 1);
            mask |= (v.z != 0 ? 1u : 0u) << (j * 4 + 2);
            mask |= (v.w != 0 ? 1u : 0u) << (j * 4 + 3);
        }
    }
    int cnt = __popc(mask);
    int inc = warp_incl_scan(cnt);
    if (lane == 31) s_w[w] = inc;
    __syncthreads();
    if (t == 0) {
        int s = 0;
#pragma unroll
        for (int j = 0; j < 8; j++) { int c = s_w[j]; s_w[j] = s; s += c; }
        s_na = s;
    }
    __syncthreads();
    {
        int pos = s_w[w] + (inc - cnt);
        unsigned mm = mask;
        while (mm) {
            int j = __ffs(mm) - 1;
            s_act[pos++] = t * 32 + j;
            mm &= mm - 1;
        }
    }
    __syncthreads();

    int na = s_na;
    int lo = ( blockIdx.y      * na) / ROW_SPLITS;
    int hi = ((blockIdx.y + 1) * na) / ROW_SPLITS;

    // --- stream active rows, 8-deep for MLP ---
    int col = (blockIdx.x * blockDim.x + t) * 4;
    const float4* pc = reinterpret_cast<const float4*>(p + col);

    unsigned c0 = 0, c1 = 0, c2 = 0, c3 = 0;
    int r = lo;
    for (; r + 8 <= hi; r += 8) {
        float4 v[8];
#pragma unroll
        for (int u = 0; u < 8; u++)
            v[u] = __ldcs(pc + (size_t)s_act[r + u] * (OUT_DIM / 4));
#pragma unroll
        for (int u = 0; u < 8; u++) {
            c0 += (v[u].x > 0.5f);
            c1 += (v[u].y > 0.5f);
            c2 += (v[u].z > 0.5f);
            c3 += (v[u].w > 0.5f);
        }
    }
    for (; r < hi; r++) {
        float4 v0 = __ldcs(pc + (size_t)s_act[r] * (OUT_DIM / 4));
        c0 += (v0.x > 0.5f);
        c1 += (v0.y > 0.5f);
        c2 += (v0.z > 0.5f);
        c3 += (v0.w > 0.5f);
    }

    unsigned cc[4] = {c0, c1, c2, c3};
#pragma unroll
    for (int u = 0; u < 4; u++) {
        unsigned old = atomicAdd(&g_overlap[col + u], CNT_ONE + cc[u]);
        if ((old >> 20) == (ROW_SPLITS - 1)) {
            int fv = (int)((old & VAL_MASK) + cc[u]);
            g_final[col + u] = fv;
            atomicAdd(&g_hist[fv], 1);
            g_overlap[col + u] = 0u;      // self-reset: last toucher
        }
    }
}

// ---------------------------------------------------------------------------
// Kernel B: 256 fully independent blocks, 64 columns each. NO atomics, NO
// inter-block sync, NO state reset. Loads the prebuilt histogram (int4),
// computes (T,R) via suffix scan, counts ties before its segment from
// g_final (int4), writes its slice with exact jax.lax.top_k tie semantics
// (lower index first).
// ---------------------------------------------------------------------------
__global__ void __launch_bounds__(256)
finalize_kernel(float* __restrict__ out) {
    __shared__ __align__(16) int s_hist[IN_DIM + 1];
    __shared__ int s_scan[256];
    __shared__ int s_w[8];
    __shared__ int s_T, s_R, s_pref;

    int t    = threadIdx.x;
    int lane = t & 31;
    int w    = t >> 5;
    int b    = blockIdx.x;
    int base = b * BCOLS;

    // --- load prebuilt histogram (no atomics) ---
    {
        const int4* h4 = reinterpret_cast<const int4*>(g_hist);
        int4* s4 = reinterpret_cast<int4*>(s_hist);
#pragma unroll
        for (int i = 0; i < 8; i++) s4[t + i * 256] = h4[t + i * 256];
        if (t == 0) s_hist[IN_DIM] = g_hist[IN_DIM];
    }
    __syncthreads();

    // --- threshold: thread t owns bins [32t, 32t+31]; t==255 also bin 8192 ---
    int b0 = t * 32;
    int csum = 0;
#pragma unroll
    for (int k = 0; k < 32; k++) csum += s_hist[b0 + k];
    if (t == 255) csum += s_hist[IN_DIM];

    s_scan[255 - t] = csum;              // reversed → prefix scan = suffix scan
    __syncthreads();
    {
        int v = s_scan[t];
        int inc = warp_incl_scan(v);
        if (lane == 31) s_w[w] = inc;
        __syncthreads();
        if (w == 0) {
            int wv = (lane < 8) ? s_w[lane] : 0;
            int winc = warp_incl_scan(wv);
            if (lane < 8) s_w[lane] = winc;
        }
        __syncthreads();
        int add = (w > 0) ? s_w[w - 1] : 0;
        s_scan[t] = inc + add;
    }
    __syncthreads();

    int above = (t == 255) ? 0 : s_scan[254 - t];
    {
        int running = above;
        int top = (t == 255) ? IN_DIM : (b0 + 31);
        for (int v = top; v >= b0; v--) {
            int prev = running;              // count(> v)
            running += s_hist[v];            // count(>= v)
            if (prev < TOPK && running >= TOPK) {
                s_T = v;
                s_R = TOPK - prev;
            }
        }
    }
    __syncthreads();
    int T = s_T;
    int R = s_R;

    // --- ties at T strictly before this segment (index order), int4 reads ---
    int cnt = 0;
    {
        const int4* f4 = reinterpret_cast<const int4*>(g_final);
        int n4 = base >> 2;                  // base is a multiple of 64
        for (int i = t; i < n4; i += 256) {
            int4 v = f4[i];
            cnt += (v.x == T) + (v.y == T) + (v.z == T) + (v.w == T);
        }
    }
#pragma unroll
    for (int o = 16; o; o >>= 1) cnt += __shfl_down_sync(0xffffffffu, cnt, o);
    if (lane == 0) s_w[w] = cnt;
    __syncthreads();
    if (t == 0) {
        int s = 0;
#pragma unroll
        for (int j = 0; j < 8; j++) s += s_w[j];
        s_pref = s;
    }
    __syncthreads();

    // --- own 64 columns: warps 0 and 1, ballot-ordered tie ranks ---
    int v = 0, flag = 0;
    unsigned m = 0;
    if (t < BCOLS) {
        v = g_final[base + t];
        flag = (v == T);
    }
    if (w < 2) m = __ballot_sync(0xffffffffu, flag);
    if (t == 0) s_w[0] = __popc(m);          // warp-0 tie count for warp 1
    __syncthreads();

    if (t < BCOLS) {
        int rank = s_pref + ((w == 1) ? s_w[0] : 0) + __popc(m & ((1u << lane) - 1u));
        float val = 0.0f;
        if (v > T) val = 1.0f;
        else if (flag && rank < R) val = 1.0f;
        out[base + t] = val;
    }
}

extern "C" void kernel_launch(void* const* d_in, const int* in_sizes, int n_in,
                              void* d_out, int out_size) {
    const int*   x = (const int*)d_in[0];
    const float* p = (const float*)d_in[1];
    if (in_sizes[0] != IN_DIM) {
        x = (const int*)d_in[1];
        p = (const float*)d_in[0];
    }
    float* out = (float*)d_out;

    dim3 grid(COL_BLOCKS, ROW_SPLITS);
    gemv_kernel<<<grid, 256>>>(p, x);
    finalize_kernel<<<BBLK, 256>>>(out);
}

// round 13
// speedup vs baseline: 1.1496x; 1.1496x over previous
#include <cuda_runtime.h>

#define IN_DIM   8192
#define OUT_DIM  16384
#define TOPK     327
#define ROW_SPLITS 46                 // 16 * 46 = 736 ≤ 148 SMs * 5 → one wave
#define ROWS_PER_SPLIT 179            // 46 * 179 = 8234 ≥ 8192
#define COL_BLOCKS 16
#define CNT_ONE  (1u << 20)
#define VAL_MASK 0xFFFFFu
#define BBLK     256                  // finalize blocks
#define BCOLS    (OUT_DIM / BBLK)     // 64 columns per finalize block

// padded smem histogram index: bank of PAD(32t+k) = (t+k)%32 → conflict-free
#define PAD(i)   ((i) + ((i) >> 5))
#define HIST_SMEM (IN_DIM + (IN_DIM >> 5) + 2)   // PAD(8192)=8448 → 8450 ints

__device__ __align__(16) unsigned g_overlap[OUT_DIM];  // packed [cnt|val]; self-resets
__device__ __align__(16) int      g_hist[IN_DIM + 1];  // zeroed at gemv start
__device__ __align__(16) int      g_final[OUT_DIM];    // fully rewritten every launch

__device__ __forceinline__ int warp_incl_scan(int v) {
    int lane = threadIdx.x & 31;
#pragma unroll
    for (int o = 1; o < 32; o <<= 1) {
        int n = __shfl_up_sync(0xffffffffu, v, o);
        if (lane >= o) v += n;
    }
    return v;
}

// ---------------------------------------------------------------------------
// Kernel A: binarized GEMV (per-slice ballot compaction, proven form).
// Zeroes g_hist at start (bids 0..32). Packed atomic accumulate; the 46th
// (last) arrival per column publishes g_final + g_hist and self-resets
// g_overlap[col]. round(p) for p ~ U[0,1) round-half-even == (p > 0.5f).
// ---------------------------------------------------------------------------
__global__ void __launch_bounds__(256, 5)
gemv_kernel(const float* __restrict__ p, const int* __restrict__ x) {
    __shared__ int s_act[ROWS_PER_SPLIT];
    __shared__ int s_wbase[8];
    __shared__ int s_na;

    int t    = threadIdx.x;
    int lane = t & 31;
    int w    = t >> 5;
    int bid  = blockIdx.y * COL_BLOCKS + blockIdx.x;

    // zero g_hist for this launch (publishes happen only much later)
    if (bid < 33) {
        int i = bid * 256 + t;
        if (i <= IN_DIM) g_hist[i] = 0;
    }

    int r0 = blockIdx.y * ROWS_PER_SPLIT;
    int r1 = min(r0 + ROWS_PER_SPLIT, IN_DIM);
    int n  = r1 - r0;

    // per-block ordered compaction of the x slice
    int flag = 0;
    if (t < n) flag = (x[r0 + t] != 0);
    unsigned m = __ballot_sync(0xffffffffu, flag);
    int pos = __popc(m & ((1u << lane) - 1u));
    if (lane == 0) s_wbase[w] = __popc(m);
    __syncthreads();
    if (t < 8) {
        int v = s_wbase[t];
        int inc = v;
#pragma unroll
        for (int o = 1; o < 8; o <<= 1) {
            int u = __shfl_up_sync(0xffu, inc, o);
            if (t >= o) inc += u;
        }
        s_wbase[t] = inc - v;
        if (t == 7) s_na = inc;
    }
    __syncthreads();
    if (flag) s_act[s_wbase[w] + pos] = r0 + t;
    __syncthreads();

    int na = s_na;
    int col = (blockIdx.x * blockDim.x + t) * 4;
    const float4* pc = reinterpret_cast<const float4*>(p + col);

    unsigned c0 = 0, c1 = 0, c2 = 0, c3 = 0;
    int r = 0;
    for (; r + 8 <= na; r += 8) {
        float4 v[8];
#pragma unroll
        for (int u = 0; u < 8; u++)
            v[u] = __ldcs(pc + (size_t)s_act[r + u] * (OUT_DIM / 4));
#pragma unroll
        for (int u = 0; u < 8; u++) {
            c0 += (v[u].x > 0.5f);
            c1 += (v[u].y > 0.5f);
            c2 += (v[u].z > 0.5f);
            c3 += (v[u].w > 0.5f);
        }
    }
    for (; r < na; r++) {
        float4 v0 = __ldcs(pc + (size_t)s_act[r] * (OUT_DIM / 4));
        c0 += (v0.x > 0.5f);
        c1 += (v0.y > 0.5f);
        c2 += (v0.z > 0.5f);
        c3 += (v0.w > 0.5f);
    }

    unsigned cc[4] = {c0, c1, c2, c3};
#pragma unroll
    for (int u = 0; u < 4; u++) {
        unsigned old = atomicAdd(&g_overlap[col + u], CNT_ONE + cc[u]);
        if ((old >> 20) == (ROW_SPLITS - 1)) {
            int fv = (int)((old & VAL_MASK) + cc[u]);
            g_final[col + u] = fv;
            atomicAdd(&g_hist[fv], 1);
            g_overlap[col + u] = 0u;      // self-reset: last toucher
        }
    }
}

// ---------------------------------------------------------------------------
// Kernel B: 256 fully independent blocks, 64 columns each. No atomics, no
// inter-block sync, no state reset. Loads the prebuilt histogram into a
// BANK-PADDED smem layout (the R12 version lost ~10us/block to 32-way
// same-bank conflicts in the bin loops), computes (T,R) via suffix scan,
// counts ties before its segment from g_final, and writes its slice with
// exact jax.lax.top_k tie semantics (lower index first).
// ---------------------------------------------------------------------------
__global__ void __launch_bounds__(256)
finalize_kernel(float* __restrict__ out) {
    __shared__ int s_hist[HIST_SMEM];    // padded: index via PAD()
    __shared__ int s_scan[256];
    __shared__ int s_w[8];
    __shared__ int s_T, s_R, s_pref;

    int t    = threadIdx.x;
    int lane = t & 31;
    int w    = t >> 5;
    int b    = blockIdx.x;
    int base = b * BCOLS;

    // load prebuilt histogram; coalesced global, conflict-free padded smem
    for (int i = t; i <= IN_DIM; i += 256)
        s_hist[PAD(i)] = g_hist[i];
    __syncthreads();

    // threshold: thread t owns bins [32t, 32t+31]; t==255 also bin 8192
    int b0 = t * 32;
    int pbase = 33 * t;                  // PAD(32t + k) == 33t + k
    int csum = 0;
#pragma unroll
    for (int k = 0; k < 32; k++) csum += s_hist[pbase + k];
    if (t == 255) csum += s_hist[PAD(IN_DIM)];

    s_scan[255 - t] = csum;              // reversed → prefix scan = suffix scan
    __syncthreads();
    {
        int v = s_scan[t];
        int inc = warp_incl_scan(v);
        if (lane == 31) s_w[w] = inc;
        __syncthreads();
        if (w == 0) {
            int wv = (lane < 8) ? s_w[lane] : 0;
            int winc = warp_incl_scan(wv);
            if (lane < 8) s_w[lane] = winc;
        }
        __syncthreads();
        int add = (w > 0) ? s_w[w - 1] : 0;
        s_scan[t] = inc + add;
    }
    __syncthreads();

    int above = (t == 255) ? 0 : s_scan[254 - t];
    {
        int running = above;
        if (t == 255) running += s_hist[PAD(IN_DIM)];   // bin 8192 first (> all chunk bins)
        for (int k = 31; k >= 0; k--) {
            int prev = running;              // count(> v)
            running += s_hist[pbase + k];    // count(>= v)
            if (prev < TOPK && running >= TOPK) {
                s_T = b0 + k;
                s_R = TOPK - prev;
            }
        }
        // handle T == 8192 (only possible holder: t==255 pre-loop state)
        if (t == 255) {
            int c8192 = s_hist[PAD(IN_DIM)];
            if (above < TOPK && above + c8192 >= TOPK) {
                s_T = IN_DIM;
                s_R = TOPK - above;
            }
        }
    }
    __syncthreads();
    int T = s_T;
    int R = s_R;

    // ties at T strictly before this segment (index order), int4 reads
    int cnt = 0;
    {
        const int4* f4 = reinterpret_cast<const int4*>(g_final);
        int n4 = base >> 2;
        for (int i = t; i < n4; i += 256) {
            int4 v = f4[i];
            cnt += (v.x == T) + (v.y == T) + (v.z == T) + (v.w == T);
        }
    }
#pragma unroll
    for (int o = 16; o; o >>= 1) cnt += __shfl_down_sync(0xffffffffu, cnt, o);
    if (lane == 0) s_w[w] = cnt;
    __syncthreads();
    if (t == 0) {
        int s = 0;
#pragma unroll
        for (int j = 0; j < 8; j++) s += s_w[j];
        s_pref = s;
    }
    __syncthreads();

    // own 64 columns: warps 0 and 1, ballot-ordered tie ranks
    int v = 0, flag = 0;
    unsigned m = 0;
    if (t < BCOLS) {
        v = g_final[base + t];
        flag = (v == T);
    }
    if (w < 2) m = __ballot_sync(0xffffffffu, flag);
    if (t == 0) s_w[0] = __popc(m);          // warp-0 tie count for warp 1
    __syncthreads();

    if (t < BCOLS) {
        int rank = s_pref + ((w == 1) ? s_w[0] : 0) + __popc(m & ((1u << lane) - 1u));
        float val = 0.0f;
        if (v > T) val = 1.0f;
        else if (flag && rank < R) val = 1.0f;
        out[base + t] = val;
    }
}

extern "C" void kernel_launch(void* const* d_in, const int* in_sizes, int n_in,
                              void* d_out, int out_size) {
    const int*   x = (const int*)d_in[0];
    const float* p = (const float*)d_in[1];
    if (in_sizes[0] != IN_DIM) {
        x = (const int*)d_in[1];
        p = (const float*)d_in[0];
    }
    float* out = (float*)d_out;

    dim3 grid(COL_BLOCKS, ROW_SPLITS);
    gemv_kernel<<<grid, 256>>>(p, x);
    finalize_kernel<<<BBLK, 256>>>(out);
}